// round 1
// baseline (speedup 1.0000x reference)
#include <cuda_runtime.h>
#include <math.h>

#define B_  8
#define S_  1024
#define D_  1024
#define H_  16
#define DH_ 64
#define M_  (B_*S_)     // 8192 rows

// Scratch (static device globals — no runtime allocation)
__device__ float g_q[(size_t)M_*D_];
__device__ float g_k[(size_t)M_*D_];
__device__ float g_v[(size_t)M_*D_];
__device__ float g_ctx[(size_t)M_*D_];

// ---------------------------------------------------------------------------
// Fused GEMM: C = epi(A[M,1024] @ W[1024,1024] + bias)
//   DO_BN=true : epi = BN(relu(x))  (inference BN, eps=1e-3)
//   DO_BN=false: epi = relu(x)
// 128x128 block tile, BK=16, 8x8 per thread, 256 threads.
// ---------------------------------------------------------------------------
template<bool DO_BN>
__global__ void __launch_bounds__(256)
gemm_epi_kernel(const float* __restrict__ A, const float* __restrict__ W,
                const float* __restrict__ bias,
                const float* __restrict__ gam, const float* __restrict__ bet,
                const float* __restrict__ mmean, const float* __restrict__ mvar,
                float* __restrict__ C)
{
    const int K = D_, N = D_;
    const int tid  = threadIdx.x;
    const int brow = blockIdx.y * 128;
    const int bcol = blockIdx.x * 128;

    __shared__ float As[16][128 + 4];
    __shared__ float Bs[16][128 + 4];

    const int arow = tid >> 2;           // 0..63
    const int acol = (tid & 3) << 2;     // 0,4,8,12
    const int wrow = tid >> 5;           // 0..7
    const int wcol = (tid & 31) << 2;    // 0..124

    const int ty = tid >> 4;             // 0..15
    const int tx = tid & 15;             // 0..15

    float acc[8][8];
    #pragma unroll
    for (int i = 0; i < 8; i++)
        #pragma unroll
        for (int j = 0; j < 8; j++) acc[i][j] = 0.f;

    for (int k0 = 0; k0 < K; k0 += 16) {
        #pragma unroll
        for (int p = 0; p < 2; p++) {
            int r = arow + p * 64;
            float4 va = *reinterpret_cast<const float4*>(
                &A[(size_t)(brow + r) * K + k0 + acol]);
            As[acol + 0][r] = va.x; As[acol + 1][r] = va.y;
            As[acol + 2][r] = va.z; As[acol + 3][r] = va.w;
        }
        #pragma unroll
        for (int p = 0; p < 2; p++) {
            int r = wrow + p * 8;
            float4 vb = *reinterpret_cast<const float4*>(
                &W[(size_t)(k0 + r) * N + bcol + wcol]);
            *reinterpret_cast<float4*>(&Bs[r][wcol]) = vb;
        }
        __syncthreads();

        #pragma unroll
        for (int kk = 0; kk < 16; kk++) {
            float ra[8], rb[8];
            #pragma unroll
            for (int i = 0; i < 8; i++) ra[i] = As[kk][ty * 8 + i];
            #pragma unroll
            for (int j = 0; j < 8; j++) rb[j] = Bs[kk][tx * 8 + j];
            #pragma unroll
            for (int i = 0; i < 8; i++)
                #pragma unroll
                for (int j = 0; j < 8; j++)
                    acc[i][j] = fmaf(ra[i], rb[j], acc[i][j]);
        }
        __syncthreads();
    }

    // Per-column epilogue params
    float pb[8], psc[8], psh[8];
    #pragma unroll
    for (int j = 0; j < 8; j++) {
        int c = bcol + tx * 8 + j;
        pb[j] = bias[c];
        if (DO_BN) {
            float sc = gam[c] * rsqrtf(mvar[c] + 1e-3f);
            psc[j] = sc;
            psh[j] = bet[c] - mmean[c] * sc;
        }
    }
    #pragma unroll
    for (int i = 0; i < 8; i++) {
        int r = brow + ty * 8 + i;
        #pragma unroll
        for (int j = 0; j < 8; j++) {
            int c = bcol + tx * 8 + j;
            float y = fmaxf(acc[i][j] + pb[j], 0.f);
            if (DO_BN) y = y * psc[j] + psh[j];
            C[(size_t)r * D_ + c] = y;
        }
    }
}

// ---------------------------------------------------------------------------
// Scores: per (b,h), S x S = (Qh @ Kh^T) * 1/8 + mask*(-1e9)
// GEMM-NT, K=64, 128x128 tile, 8x8 per thread, 256 threads. Writes into attn.
// ---------------------------------------------------------------------------
__global__ void __launch_bounds__(256)
scores_kernel(const float* __restrict__ mask, float* __restrict__ attn)
{
    const int bh = blockIdx.z;   // 0..127
    const int b  = bh >> 4;
    const int h  = bh & 15;
    const float* Aq = g_q + (size_t)b * S_ * D_ + h * DH_;
    const float* Bk = g_k + (size_t)b * S_ * D_ + h * DH_;

    const int tid  = threadIdx.x;
    const int brow = blockIdx.y * 128;
    const int bcol = blockIdx.x * 128;

    __shared__ float As[16][128 + 4];
    __shared__ float Bs[16][128 + 4];

    const int arow = tid >> 2;
    const int acol = (tid & 3) << 2;
    const int ty = tid >> 4;
    const int tx = tid & 15;

    float acc[8][8];
    #pragma unroll
    for (int i = 0; i < 8; i++)
        #pragma unroll
        for (int j = 0; j < 8; j++) acc[i][j] = 0.f;

    #pragma unroll
    for (int k0 = 0; k0 < DH_; k0 += 16) {
        #pragma unroll
        for (int p = 0; p < 2; p++) {
            int r = arow + p * 64;
            float4 va = *reinterpret_cast<const float4*>(
                &Aq[(size_t)(brow + r) * D_ + k0 + acol]);
            As[acol + 0][r] = va.x; As[acol + 1][r] = va.y;
            As[acol + 2][r] = va.z; As[acol + 3][r] = va.w;
            float4 vb = *reinterpret_cast<const float4*>(
                &Bk[(size_t)(bcol + r) * D_ + k0 + acol]);
            Bs[acol + 0][r] = vb.x; Bs[acol + 1][r] = vb.y;
            Bs[acol + 2][r] = vb.z; Bs[acol + 3][r] = vb.w;
        }
        __syncthreads();

        #pragma unroll
        for (int kk = 0; kk < 16; kk++) {
            float ra[8], rb[8];
            #pragma unroll
            for (int i = 0; i < 8; i++) ra[i] = As[kk][ty * 8 + i];
            #pragma unroll
            for (int j = 0; j < 8; j++) rb[j] = Bs[kk][tx * 8 + j];
            #pragma unroll
            for (int i = 0; i < 8; i++)
                #pragma unroll
                for (int j = 0; j < 8; j++)
                    acc[i][j] = fmaf(ra[i], rb[j], acc[i][j]);
        }
        __syncthreads();
    }

    float mk[8];
    #pragma unroll
    for (int j = 0; j < 8; j++)
        mk[j] = mask[b * S_ + bcol + tx * 8 + j] * (-1e9f);

    float* out = attn + (size_t)bh * S_ * S_;
    #pragma unroll
    for (int i = 0; i < 8; i++) {
        int r = brow + ty * 8 + i;
        #pragma unroll
        for (int j = 0; j < 8; j++) {
            int c = bcol + tx * 8 + j;
            out[(size_t)r * S_ + c] = acc[i][j] * 0.125f + mk[j];
        }
    }
}

// ---------------------------------------------------------------------------
// In-place row softmax over last dim (S_=1024). One block (128 thr) per row.
// ---------------------------------------------------------------------------
__global__ void __launch_bounds__(128)
softmax_kernel(float* __restrict__ attn)
{
    const size_t row = blockIdx.x;
    float* p = attn + row * (size_t)S_;
    const int tid  = threadIdx.x;
    const int lane = tid & 31;
    const int warp = tid >> 5;

    float v[8];
    float4 a = *reinterpret_cast<const float4*>(&p[tid * 8]);
    float4 c = *reinterpret_cast<const float4*>(&p[tid * 8 + 4]);
    v[0]=a.x; v[1]=a.y; v[2]=a.z; v[3]=a.w;
    v[4]=c.x; v[5]=c.y; v[6]=c.z; v[7]=c.w;

    float mx = v[0];
    #pragma unroll
    for (int i = 1; i < 8; i++) mx = fmaxf(mx, v[i]);
    #pragma unroll
    for (int o = 16; o; o >>= 1) mx = fmaxf(mx, __shfl_xor_sync(0xffffffffu, mx, o));

    __shared__ float smax[4], ssum[4];
    if (lane == 0) smax[warp] = mx;
    __syncthreads();
    mx = fmaxf(fmaxf(smax[0], smax[1]), fmaxf(smax[2], smax[3]));

    float s = 0.f;
    #pragma unroll
    for (int i = 0; i < 8; i++) { v[i] = __expf(v[i] - mx); s += v[i]; }
    #pragma unroll
    for (int o = 16; o; o >>= 1) s += __shfl_xor_sync(0xffffffffu, s, o);
    if (lane == 0) ssum[warp] = s;
    __syncthreads();
    s = ssum[0] + ssum[1] + ssum[2] + ssum[3];

    const float inv = 1.f / s;
    float4 oa = make_float4(v[0]*inv, v[1]*inv, v[2]*inv, v[3]*inv);
    float4 ob = make_float4(v[4]*inv, v[5]*inv, v[6]*inv, v[7]*inv);
    *reinterpret_cast<float4*>(&p[tid * 8])     = oa;
    *reinterpret_cast<float4*>(&p[tid * 8 + 4]) = ob;
}

// ---------------------------------------------------------------------------
// ctx = attn[bh] @ Vh  -> g_ctx in [B,S,D] layout (head columns interleaved)
// M=1024 (row tiles of 64), N=64, K=1024 (BK=16). 4x4 per thread, 256 threads.
// ---------------------------------------------------------------------------
__global__ void __launch_bounds__(256)
ctx_kernel(const float* __restrict__ attn)
{
    const int bh = blockIdx.y;   // 0..127
    const int b  = bh >> 4;
    const int h  = bh & 15;
    const float* A  = attn + (size_t)bh * S_ * S_;            // [1024,1024]
    const float* Bv = g_v  + (size_t)b * S_ * D_ + h * DH_;   // [1024,64], ld=D_
    float*       C  = g_ctx + (size_t)b * S_ * D_ + h * DH_;

    const int tid  = threadIdx.x;
    const int brow = blockIdx.x * 64;

    __shared__ float As[16][64 + 4];
    __shared__ float Bs[16][64 + 4];

    const int ar = tid >> 2;          // 0..63
    const int ac = (tid & 3) << 2;    // 0,4,8,12
    const int br = tid >> 4;          // 0..15
    const int bc = (tid & 15) << 2;   // 0..60

    const int ty = tid >> 4;
    const int tx = tid & 15;

    float acc[4][4];
    #pragma unroll
    for (int i = 0; i < 4; i++)
        #pragma unroll
        for (int j = 0; j < 4; j++) acc[i][j] = 0.f;

    for (int k0 = 0; k0 < S_; k0 += 16) {
        float4 va = *reinterpret_cast<const float4*>(
            &A[(size_t)(brow + ar) * S_ + k0 + ac]);
        As[ac + 0][ar] = va.x; As[ac + 1][ar] = va.y;
        As[ac + 2][ar] = va.z; As[ac + 3][ar] = va.w;

        float4 vb = *reinterpret_cast<const float4*>(
            &Bv[(size_t)(k0 + br) * D_ + bc]);
        *reinterpret_cast<float4*>(&Bs[br][bc]) = vb;
        __syncthreads();

        #pragma unroll
        for (int kk = 0; kk < 16; kk++) {
            float ra[4], rb[4];
            #pragma unroll
            for (int i = 0; i < 4; i++) ra[i] = As[kk][ty * 4 + i];
            #pragma unroll
            for (int j = 0; j < 4; j++) rb[j] = Bs[kk][tx * 4 + j];
            #pragma unroll
            for (int i = 0; i < 4; i++)
                #pragma unroll
                for (int j = 0; j < 4; j++)
                    acc[i][j] = fmaf(ra[i], rb[j], acc[i][j]);
        }
        __syncthreads();
    }

    #pragma unroll
    for (int i = 0; i < 4; i++)
        #pragma unroll
        for (int j = 0; j < 4; j++)
            C[(size_t)(brow + ty * 4 + i) * D_ + tx * 4 + j] = acc[i][j];
}

// ---------------------------------------------------------------------------
extern "C" void kernel_launch(void* const* d_in, const int* in_sizes, int n_in,
                              void* d_out, int out_size)
{
    const float* q    = (const float*)d_in[0];
    const float* k    = (const float*)d_in[1];
    const float* v    = (const float*)d_in[2];
    const float* mask = (const float*)d_in[3];
    const float* wq = (const float*)d_in[4];  const float* bq = (const float*)d_in[5];
    const float* wk = (const float*)d_in[6];  const float* bk = (const float*)d_in[7];
    const float* wv = (const float*)d_in[8];  const float* bv = (const float*)d_in[9];
    const float* wo = (const float*)d_in[10]; const float* bo = (const float*)d_in[11];
    const float* g1 = (const float*)d_in[12]; const float* be1 = (const float*)d_in[13];
    const float* mm1 = (const float*)d_in[14]; const float* mv1 = (const float*)d_in[15];
    const float* g2 = (const float*)d_in[16]; const float* be2 = (const float*)d_in[17];
    const float* mm2 = (const float*)d_in[18]; const float* mv2 = (const float*)d_in[19];
    const float* g3 = (const float*)d_in[20]; const float* be3 = (const float*)d_in[21];
    const float* mm3 = (const float*)d_in[22]; const float* mv3 = (const float*)d_in[23];

    float* out  = (float*)d_out;
    float* attn = out + (size_t)M_ * D_;   // attn follows out in d_out

    void* p;
    cudaGetSymbolAddress(&p, g_q);   float* gq = (float*)p;
    cudaGetSymbolAddress(&p, g_k);   float* gk = (float*)p;
    cudaGetSymbolAddress(&p, g_v);   float* gv = (float*)p;
    cudaGetSymbolAddress(&p, g_ctx); float* gc = (float*)p;

    dim3 gp(D_ / 128, M_ / 128);   // (8, 64)
    gemm_epi_kernel<true><<<gp, 256>>>(q, wq, bq, g1, be1, mm1, mv1, gq);
    gemm_epi_kernel<true><<<gp, 256>>>(k, wk, bk, g2, be2, mm2, mv2, gk);
    gemm_epi_kernel<true><<<gp, 256>>>(v, wv, bv, g3, be3, mm3, mv3, gv);

    dim3 gs(S_ / 128, S_ / 128, B_ * H_);  // (8, 8, 128)
    scores_kernel<<<gs, 256>>>(mask, attn);

    softmax_kernel<<<(unsigned)((size_t)B_ * H_ * S_), 128>>>(attn);

    dim3 gc2(S_ / 64, B_ * H_);            // (16, 128)
    ctx_kernel<<<gc2, 256>>>(attn);

    gemm_epi_kernel<false><<<gp, 256>>>(gc, wo, bo, nullptr, nullptr, nullptr, nullptr, out);
}

// round 3
// speedup vs baseline: 2.4935x; 2.4935x over previous
#include <cuda_runtime.h>
#include <cuda_bf16.h>
#include <stdint.h>
#include <math.h>

#define B_  8
#define S_  1024
#define D_  1024
#define H_  16
#define DH_ 64
#define M_  (B_*S_)     // 8192

// Split bf16 scratch planes (hi/lo) — no runtime allocation
__device__ __nv_bfloat16 g_qh[(size_t)M_*D_], g_ql[(size_t)M_*D_];
__device__ __nv_bfloat16 g_kh[(size_t)M_*D_], g_kl[(size_t)M_*D_];
__device__ __nv_bfloat16 g_vh[(size_t)M_*D_], g_vl[(size_t)M_*D_];
__device__ __nv_bfloat16 g_ch[(size_t)M_*D_], g_cl[(size_t)M_*D_];

// ---------------------------------------------------------------------------
// helpers
// ---------------------------------------------------------------------------
__device__ __forceinline__ uint32_t cvta_s(const void* p) {
    return (uint32_t)__cvta_generic_to_shared(p);
}
__device__ __forceinline__ void ldsm4(uint32_t r[4], uint32_t a) {
    asm volatile("ldmatrix.sync.aligned.m8n8.x4.shared.b16 {%0,%1,%2,%3}, [%4];"
        : "=r"(r[0]), "=r"(r[1]), "=r"(r[2]), "=r"(r[3]) : "r"(a));
}
__device__ __forceinline__ void ldsm4t(uint32_t r[4], uint32_t a) {
    asm volatile("ldmatrix.sync.aligned.m8n8.x4.trans.shared.b16 {%0,%1,%2,%3}, [%4];"
        : "=r"(r[0]), "=r"(r[1]), "=r"(r[2]), "=r"(r[3]) : "r"(a));
}
__device__ __forceinline__ void mma_bf(float c[4], const uint32_t a[4],
                                       uint32_t b0, uint32_t b1) {
    asm volatile("mma.sync.aligned.m16n8k16.row.col.f32.bf16.bf16.f32 "
        "{%0,%1,%2,%3},{%4,%5,%6,%7},{%8,%9},{%0,%1,%2,%3};"
        : "+f"(c[0]), "+f"(c[1]), "+f"(c[2]), "+f"(c[3])
        : "r"(a[0]), "r"(a[1]), "r"(a[2]), "r"(a[3]), "r"(b0), "r"(b1));
}
__device__ __forceinline__ void split_bf(float x, __nv_bfloat16& h, __nv_bfloat16& l) {
    h = __float2bfloat16(x);
    l = __float2bfloat16(x - __bfloat162float(h));
}

// ---------------------------------------------------------------------------
// Tensor-core GEMM: C = epi(A[8192,1024] @ W[1024,1024] + bias)
// 128x128 block tile, K-slab 32, 8 warps, warp tile 32x64.
// A_SPLIT: A supplied as bf16 hi/lo planes.  SPLIT_OUT: write bf16 hi/lo.
// ---------------------------------------------------------------------------
template<bool DO_BN, bool SPLIT_OUT, bool A_SPLIT>
__global__ void __launch_bounds__(256)
gemm_tc(const float* __restrict__ Af,
        const __nv_bfloat16* __restrict__ Ahg, const __nv_bfloat16* __restrict__ Alg,
        const float* __restrict__ W, const float* __restrict__ bias,
        const float* __restrict__ gam, const float* __restrict__ bet,
        const float* __restrict__ mmean, const float* __restrict__ mvar,
        float* __restrict__ Cf,
        __nv_bfloat16* __restrict__ Chg, __nv_bfloat16* __restrict__ Clg)
{
    __shared__ __align__(16) __nv_bfloat16 sAh[128*40], sAl[128*40];
    __shared__ __align__(16) __nv_bfloat16 sBh[32*136], sBl[32*136];

    const int tid = threadIdx.x, lane = tid & 31, warp = tid >> 5;
    const int brow = blockIdx.y * 128, bcol = blockIdx.x * 128;

    float4 stA[4]; uint4 stAh[2], stAl[2]; float4 stB[4];

    auto loadG = [&](int ks) {
        if constexpr (!A_SPLIT) {
            #pragma unroll
            for (int p = 0; p < 4; p++) {
                int row = (tid >> 3) + 32 * p, col = (tid & 7) * 4;
                stA[p] = *(const float4*)&Af[(size_t)(brow + row) * D_ + ks + col];
            }
        } else {
            #pragma unroll
            for (int p = 0; p < 2; p++) {
                int idx = tid + 256 * p; int row = idx >> 2, ch = (idx & 3) * 8;
                stAh[p] = *(const uint4*)&Ahg[(size_t)(brow + row) * D_ + ks + ch];
                stAl[p] = *(const uint4*)&Alg[(size_t)(brow + row) * D_ + ks + ch];
            }
        }
        #pragma unroll
        for (int p = 0; p < 4; p++) {
            int row = (tid >> 5) + 8 * p, col = (tid & 31) * 4;
            stB[p] = *(const float4*)&W[(size_t)(ks + row) * D_ + bcol + col];
        }
    };
    auto storeS = [&]() {
        if constexpr (!A_SPLIT) {
            #pragma unroll
            for (int p = 0; p < 4; p++) {
                int row = (tid >> 3) + 32 * p, col = (tid & 7) * 4;
                float v[4] = {stA[p].x, stA[p].y, stA[p].z, stA[p].w};
                __nv_bfloat16 h[4], l[4];
                #pragma unroll
                for (int i = 0; i < 4; i++) split_bf(v[i], h[i], l[i]);
                *(__nv_bfloat162*)&sAh[row*40 + col]     = __halves2bfloat162(h[0], h[1]);
                *(__nv_bfloat162*)&sAh[row*40 + col + 2] = __halves2bfloat162(h[2], h[3]);
                *(__nv_bfloat162*)&sAl[row*40 + col]     = __halves2bfloat162(l[0], l[1]);
                *(__nv_bfloat162*)&sAl[row*40 + col + 2] = __halves2bfloat162(l[2], l[3]);
            }
        } else {
            #pragma unroll
            for (int p = 0; p < 2; p++) {
                int idx = tid + 256 * p; int row = idx >> 2, ch = (idx & 3) * 8;
                *(uint4*)&sAh[row*40 + ch] = stAh[p];
                *(uint4*)&sAl[row*40 + ch] = stAl[p];
            }
        }
        #pragma unroll
        for (int p = 0; p < 4; p++) {
            int row = (tid >> 5) + 8 * p, col = (tid & 31) * 4;
            float v[4] = {stB[p].x, stB[p].y, stB[p].z, stB[p].w};
            __nv_bfloat16 h[4], l[4];
            #pragma unroll
            for (int i = 0; i < 4; i++) split_bf(v[i], h[i], l[i]);
            *(__nv_bfloat162*)&sBh[row*136 + col]     = __halves2bfloat162(h[0], h[1]);
            *(__nv_bfloat162*)&sBh[row*136 + col + 2] = __halves2bfloat162(h[2], h[3]);
            *(__nv_bfloat162*)&sBl[row*136 + col]     = __halves2bfloat162(l[0], l[1]);
            *(__nv_bfloat162*)&sBl[row*136 + col + 2] = __halves2bfloat162(l[2], l[3]);
        }
    };

    const int wm = warp >> 1, wn = warp & 1;
    const int m0 = wm * 32, n0 = wn * 64;

    float acc[2][8][4];
    #pragma unroll
    for (int i = 0; i < 2; i++)
        #pragma unroll
        for (int j = 0; j < 8; j++)
            #pragma unroll
            for (int q = 0; q < 4; q++) acc[i][j][q] = 0.f;

    loadG(0);
    for (int ks = 0; ks < D_; ks += 32) {
        storeS();
        __syncthreads();
        if (ks + 32 < D_) loadG(ks + 32);

        #pragma unroll
        for (int kk = 0; kk < 32; kk += 16) {
            uint32_t ah[2][4], al[2][4];
            #pragma unroll
            for (int mi = 0; mi < 2; mi++) {
                int off = (m0 + mi*16 + (lane & 15)) * 40 + kk + ((lane >> 4) << 3);
                ldsm4(ah[mi], cvta_s(&sAh[off]));
                ldsm4(al[mi], cvta_s(&sAl[off]));
            }
            #pragma unroll
            for (int nj = 0; nj < 4; nj++) {
                uint32_t bh[4], bl[4];
                int off = (kk + (lane & 15)) * 136 + n0 + nj*16 + ((lane >> 4) << 3);
                ldsm4t(bh, cvta_s(&sBh[off]));
                ldsm4t(bl, cvta_s(&sBl[off]));
                #pragma unroll
                for (int mi = 0; mi < 2; mi++) {
                    mma_bf(acc[mi][2*nj],   ah[mi], bh[0], bh[1]);
                    mma_bf(acc[mi][2*nj],   ah[mi], bl[0], bl[1]);
                    mma_bf(acc[mi][2*nj],   al[mi], bh[0], bh[1]);
                    mma_bf(acc[mi][2*nj+1], ah[mi], bh[2], bh[3]);
                    mma_bf(acc[mi][2*nj+1], ah[mi], bl[2], bl[3]);
                    mma_bf(acc[mi][2*nj+1], al[mi], bh[2], bh[3]);
                }
            }
        }
        __syncthreads();
    }

    // epilogue
    #pragma unroll
    for (int mi = 0; mi < 2; mi++) {
        int r0 = brow + m0 + mi*16 + (lane >> 2);
        #pragma unroll
        for (int nj = 0; nj < 8; nj++) {
            int c = bcol + n0 + nj*8 + (lane & 3)*2;
            float b0v = bias[c], b1v = bias[c+1];
            float sc0 = 1.f, sh0 = 0.f, sc1 = 1.f, sh1 = 0.f;
            if (DO_BN) {
                sc0 = gam[c]   * rsqrtf(mvar[c]   + 1e-3f); sh0 = bet[c]   - mmean[c]   * sc0;
                sc1 = gam[c+1] * rsqrtf(mvar[c+1] + 1e-3f); sh1 = bet[c+1] - mmean[c+1] * sc1;
            }
            float y00 = fmaxf(acc[mi][nj][0] + b0v, 0.f);
            float y01 = fmaxf(acc[mi][nj][1] + b1v, 0.f);
            float y10 = fmaxf(acc[mi][nj][2] + b0v, 0.f);
            float y11 = fmaxf(acc[mi][nj][3] + b1v, 0.f);
            if (DO_BN) {
                y00 = y00*sc0 + sh0; y01 = y01*sc1 + sh1;
                y10 = y10*sc0 + sh0; y11 = y11*sc1 + sh1;
            }
            if constexpr (SPLIT_OUT) {
                __nv_bfloat16 h0,l0,h1,l1,h2,l2,h3,l3;
                split_bf(y00,h0,l0); split_bf(y01,h1,l1);
                split_bf(y10,h2,l2); split_bf(y11,h3,l3);
                *(__nv_bfloat162*)&Chg[(size_t)r0*D_ + c]     = __halves2bfloat162(h0,h1);
                *(__nv_bfloat162*)&Clg[(size_t)r0*D_ + c]     = __halves2bfloat162(l0,l1);
                *(__nv_bfloat162*)&Chg[(size_t)(r0+8)*D_ + c] = __halves2bfloat162(h2,h3);
                *(__nv_bfloat162*)&Clg[(size_t)(r0+8)*D_ + c] = __halves2bfloat162(l2,l3);
            } else {
                *(float2*)&Cf[(size_t)r0*D_ + c]     = make_float2(y00, y01);
                *(float2*)&Cf[(size_t)(r0+8)*D_ + c] = make_float2(y10, y11);
            }
        }
    }
}

// ---------------------------------------------------------------------------
// scores: per (b,h): (Qh @ Kh^T)*0.125 + mask*(-1e9)  [tensor cores, K=64]
// 128x128 tile, split bf16 inputs pre-staged in gmem. Single load phase.
// ---------------------------------------------------------------------------
__global__ void __launch_bounds__(256)
scores_tc(const float* __restrict__ mask, float* __restrict__ attn)
{
    extern __shared__ __align__(16) __nv_bfloat16 sm[];
    __nv_bfloat16* sQh = sm;
    __nv_bfloat16* sQl = sm + 9216;
    __nv_bfloat16* sKh = sm + 18432;
    __nv_bfloat16* sKl = sm + 27648;

    const int bh = blockIdx.z, b = bh >> 4, h = bh & 15;
    const size_t base = (size_t)b * S_ * D_ + h * DH_;
    const int tid = threadIdx.x, lane = tid & 31, warp = tid >> 5;
    const int brow = blockIdx.y * 128, bcol = blockIdx.x * 128;

    // FIXED loader: full 128 rows x 64 depth cols per plane
    #pragma unroll
    for (int p = 0; p < 4; p++) {
        int idx = tid + 256 * p;          // 0..1023
        int row = idx >> 3;               // 0..127
        int ch  = (idx & 7) * 8;          // 0..56
        *(uint4*)&sQh[row*72 + ch] = *(const uint4*)&g_qh[base + (size_t)(brow + row)*D_ + ch];
        *(uint4*)&sQl[row*72 + ch] = *(const uint4*)&g_ql[base + (size_t)(brow + row)*D_ + ch];
        *(uint4*)&sKh[row*72 + ch] = *(const uint4*)&g_kh[base + (size_t)(bcol + row)*D_ + ch];
        *(uint4*)&sKl[row*72 + ch] = *(const uint4*)&g_kl[base + (size_t)(bcol + row)*D_ + ch];
    }
    __syncthreads();

    const int wm = warp >> 1, wn = warp & 1;
    const int m0 = wm * 32, n0 = wn * 64;

    float acc[2][8][4];
    #pragma unroll
    for (int i = 0; i < 2; i++)
        #pragma unroll
        for (int j = 0; j < 8; j++)
            #pragma unroll
            for (int q = 0; q < 4; q++) acc[i][j][q] = 0.f;

    #pragma unroll
    for (int kk = 0; kk < 64; kk += 16) {
        uint32_t ah[2][4], al[2][4];
        #pragma unroll
        for (int mi = 0; mi < 2; mi++) {
            int off = (m0 + mi*16 + (lane & 15)) * 72 + kk + ((lane >> 4) << 3);
            ldsm4(ah[mi], cvta_s(&sQh[off]));
            ldsm4(al[mi], cvta_s(&sQl[off]));
        }
        #pragma unroll
        for (int nj = 0; nj < 4; nj++) {
            // non-trans B frags from [n][k] storage
            int nr = n0 + nj*16 + ((lane & 7) | (((lane >> 4) & 1) << 3));
            int off = nr * 72 + kk + (((lane >> 3) & 1) << 3);
            uint32_t bh[4], bl[4];
            ldsm4(bh, cvta_s(&sKh[off]));
            ldsm4(bl, cvta_s(&sKl[off]));
            #pragma unroll
            for (int mi = 0; mi < 2; mi++) {
                mma_bf(acc[mi][2*nj],   ah[mi], bh[0], bh[1]);
                mma_bf(acc[mi][2*nj],   ah[mi], bl[0], bl[1]);
                mma_bf(acc[mi][2*nj],   al[mi], bh[0], bh[1]);
                mma_bf(acc[mi][2*nj+1], ah[mi], bh[2], bh[3]);
                mma_bf(acc[mi][2*nj+1], ah[mi], bl[2], bl[3]);
                mma_bf(acc[mi][2*nj+1], al[mi], bh[2], bh[3]);
            }
        }
    }

    float* outp = attn + (size_t)bh * S_ * S_;
    #pragma unroll
    for (int mi = 0; mi < 2; mi++) {
        int r0 = brow + m0 + mi*16 + (lane >> 2);
        #pragma unroll
        for (int nj = 0; nj < 8; nj++) {
            int c = bcol + n0 + nj*8 + (lane & 3)*2;
            float mv0 = mask[b*S_ + c]     * (-1e9f);
            float mv1 = mask[b*S_ + c + 1] * (-1e9f);
            *(float2*)&outp[(size_t)r0*S_ + c] =
                make_float2(acc[mi][nj][0]*0.125f + mv0, acc[mi][nj][1]*0.125f + mv1);
            *(float2*)&outp[(size_t)(r0+8)*S_ + c] =
                make_float2(acc[mi][nj][2]*0.125f + mv0, acc[mi][nj][3]*0.125f + mv1);
        }
    }
}

// ---------------------------------------------------------------------------
// In-place row softmax (row = 1024 floats), 128 threads/row.
// ---------------------------------------------------------------------------
__global__ void __launch_bounds__(128)
softmax_kernel(float* __restrict__ attn)
{
    const size_t row = blockIdx.x;
    float* p = attn + row * (size_t)S_;
    const int tid = threadIdx.x, lane = tid & 31, warp = tid >> 5;

    float v[8];
    float4 a = *reinterpret_cast<const float4*>(&p[tid*8]);
    float4 c = *reinterpret_cast<const float4*>(&p[tid*8 + 4]);
    v[0]=a.x; v[1]=a.y; v[2]=a.z; v[3]=a.w;
    v[4]=c.x; v[5]=c.y; v[6]=c.z; v[7]=c.w;

    float mx = v[0];
    #pragma unroll
    for (int i = 1; i < 8; i++) mx = fmaxf(mx, v[i]);
    #pragma unroll
    for (int o = 16; o; o >>= 1) mx = fmaxf(mx, __shfl_xor_sync(0xffffffffu, mx, o));

    __shared__ float smax[4], ssum[4];
    if (lane == 0) smax[warp] = mx;
    __syncthreads();
    mx = fmaxf(fmaxf(smax[0], smax[1]), fmaxf(smax[2], smax[3]));

    float s = 0.f;
    #pragma unroll
    for (int i = 0; i < 8; i++) { v[i] = __expf(v[i] - mx); s += v[i]; }
    #pragma unroll
    for (int o = 16; o; o >>= 1) s += __shfl_xor_sync(0xffffffffu, s, o);
    if (lane == 0) ssum[warp] = s;
    __syncthreads();
    s = ssum[0] + ssum[1] + ssum[2] + ssum[3];

    const float inv = 1.f / s;
    *(float4*)&p[tid*8]     = make_float4(v[0]*inv, v[1]*inv, v[2]*inv, v[3]*inv);
    *(float4*)&p[tid*8 + 4] = make_float4(v[4]*inv, v[5]*inv, v[6]*inv, v[7]*inv);
}

// ---------------------------------------------------------------------------
// ctx = attn[bh] @ Vh -> split bf16 into g_ch/g_cl ([B,S,D] layout)
// Block 128x64, K-slab 32 over 1024. attn fp32 split on the fly; V pre-split.
// ---------------------------------------------------------------------------
__global__ void __launch_bounds__(256)
ctx_tc(const float* __restrict__ attn)
{
    __shared__ __align__(16) __nv_bfloat16 sAh[128*40], sAl[128*40];
    __shared__ __align__(16) __nv_bfloat16 sBh[32*72],  sBl[32*72];

    const int bh = blockIdx.y, b = bh >> 4, h = bh & 15;
    const float* A = attn + (size_t)bh * S_ * S_;
    const __nv_bfloat16* Vh = g_vh + (size_t)b * S_ * D_ + h * DH_;
    const __nv_bfloat16* Vl = g_vl + (size_t)b * S_ * D_ + h * DH_;

    const int tid = threadIdx.x, lane = tid & 31, warp = tid >> 5;
    const int brow = blockIdx.x * 128;

    float4 stA[4]; uint4 stB[2];
    auto loadG = [&](int ks) {
        #pragma unroll
        for (int p = 0; p < 4; p++) {
            int row = (tid >> 3) + 32 * p, col = (tid & 7) * 4;
            stA[p] = *(const float4*)&A[(size_t)(brow + row) * S_ + ks + col];
        }
        // FIXED loader: 2 planes x 32 rows x 64 cols (512 uint4 total, 2/thread)
        #pragma unroll
        for (int p = 0; p < 2; p++) {
            int idx = tid + 256 * p;                 // 0..511
            int r  = (idx & 255) >> 3;               // 0..31
            int ch = (idx & 7) * 8;                  // 0..56
            const __nv_bfloat16* src = (idx < 256) ? Vh : Vl;
            stB[p] = *(const uint4*)&src[(size_t)(ks + r) * D_ + ch];
        }
    };
    auto storeS = [&]() {
        #pragma unroll
        for (int p = 0; p < 4; p++) {
            int row = (tid >> 3) + 32 * p, col = (tid & 7) * 4;
            float v[4] = {stA[p].x, stA[p].y, stA[p].z, stA[p].w};
            __nv_bfloat16 hh[4], ll[4];
            #pragma unroll
            for (int i = 0; i < 4; i++) split_bf(v[i], hh[i], ll[i]);
            *(__nv_bfloat162*)&sAh[row*40 + col]     = __halves2bfloat162(hh[0], hh[1]);
            *(__nv_bfloat162*)&sAh[row*40 + col + 2] = __halves2bfloat162(hh[2], hh[3]);
            *(__nv_bfloat162*)&sAl[row*40 + col]     = __halves2bfloat162(ll[0], ll[1]);
            *(__nv_bfloat162*)&sAl[row*40 + col + 2] = __halves2bfloat162(ll[2], ll[3]);
        }
        #pragma unroll
        for (int p = 0; p < 2; p++) {
            int idx = tid + 256 * p;
            int r  = (idx & 255) >> 3;
            int ch = (idx & 7) * 8;
            __nv_bfloat16* dst = (idx < 256) ? sBh : sBl;
            *(uint4*)&dst[r*72 + ch] = stB[p];
        }
    };

    const int wm = warp >> 1, wn = warp & 1;
    const int m0 = wm * 32, n0 = wn * 32;

    float acc[2][4][4];
    #pragma unroll
    for (int i = 0; i < 2; i++)
        #pragma unroll
        for (int j = 0; j < 4; j++)
            #pragma unroll
            for (int q = 0; q < 4; q++) acc[i][j][q] = 0.f;

    loadG(0);
    for (int ks = 0; ks < S_; ks += 32) {
        storeS();
        __syncthreads();
        if (ks + 32 < S_) loadG(ks + 32);

        #pragma unroll
        for (int kk = 0; kk < 32; kk += 16) {
            uint32_t ah[2][4], al[2][4];
            #pragma unroll
            for (int mi = 0; mi < 2; mi++) {
                int off = (m0 + mi*16 + (lane & 15)) * 40 + kk + ((lane >> 4) << 3);
                ldsm4(ah[mi], cvta_s(&sAh[off]));
                ldsm4(al[mi], cvta_s(&sAl[off]));
            }
            #pragma unroll
            for (int nj = 0; nj < 2; nj++) {
                uint32_t bh[4], bl[4];
                int off = (kk + (lane & 15)) * 72 + n0 + nj*16 + ((lane >> 4) << 3);
                ldsm4t(bh, cvta_s(&sBh[off]));
                ldsm4t(bl, cvta_s(&sBl[off]));
                #pragma unroll
                for (int mi = 0; mi < 2; mi++) {
                    mma_bf(acc[mi][2*nj],   ah[mi], bh[0], bh[1]);
                    mma_bf(acc[mi][2*nj],   ah[mi], bl[0], bl[1]);
                    mma_bf(acc[mi][2*nj],   al[mi], bh[0], bh[1]);
                    mma_bf(acc[mi][2*nj+1], ah[mi], bh[2], bh[3]);
                    mma_bf(acc[mi][2*nj+1], ah[mi], bl[2], bl[3]);
                    mma_bf(acc[mi][2*nj+1], al[mi], bh[2], bh[3]);
                }
            }
        }
        __syncthreads();
    }

    __nv_bfloat16* Ch = g_ch + (size_t)b * S_ * D_ + h * DH_;
    __nv_bfloat16* Cl = g_cl + (size_t)b * S_ * D_ + h * DH_;
    #pragma unroll
    for (int mi = 0; mi < 2; mi++) {
        int r0 = brow + m0 + mi*16 + (lane >> 2);
        #pragma unroll
        for (int nj = 0; nj < 4; nj++) {
            int c = n0 + nj*8 + (lane & 3)*2;
            __nv_bfloat16 h0,l0,h1,l1,h2,l2,h3,l3;
            split_bf(acc[mi][nj][0], h0, l0); split_bf(acc[mi][nj][1], h1, l1);
            split_bf(acc[mi][nj][2], h2, l2); split_bf(acc[mi][nj][3], h3, l3);
            *(__nv_bfloat162*)&Ch[(size_t)r0*D_ + c]     = __halves2bfloat162(h0, h1);
            *(__nv_bfloat162*)&Cl[(size_t)r0*D_ + c]     = __halves2bfloat162(l0, l1);
            *(__nv_bfloat162*)&Ch[(size_t)(r0+8)*D_ + c] = __halves2bfloat162(h2, h3);
            *(__nv_bfloat162*)&Cl[(size_t)(r0+8)*D_ + c] = __halves2bfloat162(l2, l3);
        }
    }
}

// ---------------------------------------------------------------------------
extern "C" void kernel_launch(void* const* d_in, const int* in_sizes, int n_in,
                              void* d_out, int out_size)
{
    const float* q    = (const float*)d_in[0];
    const float* k    = (const float*)d_in[1];
    const float* v    = (const float*)d_in[2];
    const float* mask = (const float*)d_in[3];
    const float* wq = (const float*)d_in[4];  const float* bq = (const float*)d_in[5];
    const float* wk = (const float*)d_in[6];  const float* bk = (const float*)d_in[7];
    const float* wv = (const float*)d_in[8];  const float* bv = (const float*)d_in[9];
    const float* wo = (const float*)d_in[10]; const float* bo = (const float*)d_in[11];
    const float* g1 = (const float*)d_in[12]; const float* be1 = (const float*)d_in[13];
    const float* mm1 = (const float*)d_in[14]; const float* mv1 = (const float*)d_in[15];
    const float* g2 = (const float*)d_in[16]; const float* be2 = (const float*)d_in[17];
    const float* mm2 = (const float*)d_in[18]; const float* mv2 = (const float*)d_in[19];
    const float* g3 = (const float*)d_in[20]; const float* be3 = (const float*)d_in[21];
    const float* mm3 = (const float*)d_in[22]; const float* mv3 = (const float*)d_in[23];

    float* out  = (float*)d_out;
    float* attn = out + (size_t)M_ * D_;

    void* p;
    __nv_bfloat16 *qh,*ql,*kh,*kl,*vh,*vl,*ch,*cl;
    cudaGetSymbolAddress(&p, g_qh); qh = (__nv_bfloat16*)p;
    cudaGetSymbolAddress(&p, g_ql); ql = (__nv_bfloat16*)p;
    cudaGetSymbolAddress(&p, g_kh); kh = (__nv_bfloat16*)p;
    cudaGetSymbolAddress(&p, g_kl); kl = (__nv_bfloat16*)p;
    cudaGetSymbolAddress(&p, g_vh); vh = (__nv_bfloat16*)p;
    cudaGetSymbolAddress(&p, g_vl); vl = (__nv_bfloat16*)p;
    cudaGetSymbolAddress(&p, g_ch); ch = (__nv_bfloat16*)p;
    cudaGetSymbolAddress(&p, g_cl); cl = (__nv_bfloat16*)p;

    dim3 gp(D_/128, M_/128);   // (8, 64)
    gemm_tc<true,true,false><<<gp,256>>>(q, nullptr, nullptr, wq, bq, g1, be1, mm1, mv1,
                                         nullptr, qh, ql);
    gemm_tc<true,true,false><<<gp,256>>>(k, nullptr, nullptr, wk, bk, g2, be2, mm2, mv2,
                                         nullptr, kh, kl);
    gemm_tc<true,true,false><<<gp,256>>>(v, nullptr, nullptr, wv, bv, g3, be3, mm3, mv3,
                                         nullptr, vh, vl);

    cudaFuncSetAttribute(scores_tc, cudaFuncAttributeMaxDynamicSharedMemorySize, 73728);
    scores_tc<<<dim3(8,8,128),256,73728>>>(mask, attn);

    softmax_kernel<<<(unsigned)((size_t)B_*H_*S_),128>>>(attn);

    ctx_tc<<<dim3(8,128),256>>>(attn);

    gemm_tc<false,false,true><<<gp,256>>>(nullptr, ch, cl, wo, bo,
                                          nullptr, nullptr, nullptr, nullptr,
                                          out, nullptr, nullptr);
}